// round 1
// baseline (speedup 1.0000x reference)
#include <cuda_runtime.h>

#define B   32
#define T   100
#define V   10000
#define D   128
#define OUTN 1000
#define BT  (B*T)

typedef unsigned long long u64;

// ---------------- scratch (no allocations allowed) ----------------
__device__ float d_e[BT * D];          // embedded visits [B*T][128]
__device__ int   d_mask[BT];           // visit mask
__device__ float d_x3[BT * 768];       // input-side gates, [bt][dir*384 + g]
__device__ float d_hs[2 * BT * D];     // GRU outputs, dir-major
__device__ float d_feat[B * D];        // combined feature

// ---------------- helpers ----------------
__device__ __forceinline__ u64 ffma2(u64 a, u64 b, u64 c) {
    u64 d;
    asm("fma.rn.f32x2 %0, %1, %2, %3;" : "=l"(d) : "l"(a), "l"(b), "l"(c));
    return d;
}
__device__ __forceinline__ float2 u2f2(u64 a) {
    float2 f;
    asm("mov.b64 {%0, %1}, %2;" : "=f"(f.x), "=f"(f.y) : "l"(a));
    return f;
}
__device__ __forceinline__ float sigmoidf(float x) { return 1.0f / (1.0f + expf(-x)); }

// ---------------- 1) sparse embedding + mask ----------------
// grid = BT blocks, 128 threads
__global__ void embed_kernel(const float* __restrict__ x, const float* __restrict__ emb) {
    int bt = blockIdx.x;
    __shared__ int cnt;
    __shared__ int idx[1024];
    if (threadIdx.x == 0) cnt = 0;
    __syncthreads();

    const float4* row = reinterpret_cast<const float4*>(x + (size_t)bt * V);
    for (int i = threadIdx.x; i < V / 4; i += blockDim.x) {
        float4 v = row[i];
        if (v.x != 0.f) { int p = atomicAdd(&cnt, 1); if (p < 1024) idx[p] = 4 * i; }
        if (v.y != 0.f) { int p = atomicAdd(&cnt, 1); if (p < 1024) idx[p] = 4 * i + 1; }
        if (v.z != 0.f) { int p = atomicAdd(&cnt, 1); if (p < 1024) idx[p] = 4 * i + 2; }
        if (v.w != 0.f) { int p = atomicAdd(&cnt, 1); if (p < 1024) idx[p] = 4 * i + 3; }
    }
    __syncthreads();
    int n = min(cnt, 1024);
    int d = threadIdx.x;  // 128 threads = 128 dims
    float acc = 0.f;
    for (int j = 0; j < n; j++) acc += emb[(size_t)idx[j] * D + d];
    d_e[bt * D + d] = acc;
    int nz = __syncthreads_or(acc != 0.f);
    if (threadIdx.x == 0) d_mask[bt] = nz ? 1 : 0;
}

// ---------------- 2) x3 = e @ wih^T + bih, both dirs ----------------
// grid (100, 8, 2), 256 threads. tile: 32 bt-rows x 48 gate-cols, K=128.
#define ES 130  // padded row stride (words)
__global__ void xgemm_kernel(const float* __restrict__ wih_f, const float* __restrict__ wih_b,
                             const float* __restrict__ bih_f, const float* __restrict__ bih_b) {
    const int bt0  = blockIdx.x * 32;
    const int col0 = blockIdx.y * 48;
    const int dir  = blockIdx.z;
    const float* W  = dir ? wih_b : wih_f;
    const float* bi = dir ? bih_b : bih_f;

    __shared__ __align__(16) float e_sh[32 * ES];
    __shared__ __align__(16) float w_sh[48 * ES];
    int tid = threadIdx.x;
    for (int i = tid; i < 32 * 128; i += 256) {
        int r = i >> 7, k = i & 127;
        e_sh[r * ES + k] = d_e[(bt0 + r) * D + k];
    }
    for (int i = tid; i < 48 * 128; i += 256) {
        int c = i >> 7, k = i & 127;
        w_sh[c * ES + k] = W[(size_t)(col0 + c) * D + k];
    }
    __syncthreads();

    int rt = tid & 15;   // rows 2*rt, 2*rt+1
    int ct = tid >> 4;   // cols 3*ct .. 3*ct+2
    int r0 = rt * 2, c0 = ct * 3;

    u64 accP[2][3] = {}, accQ[2][3] = {};
    for (int k = 0; k < 128; k += 4) {
        u64 eA[2], eB[2], wA[3], wB[3];
#pragma unroll
        for (int i = 0; i < 2; i++) {
            const u64* p = reinterpret_cast<const u64*>(&e_sh[(r0 + i) * ES + k]);
            eA[i] = p[0]; eB[i] = p[1];
        }
#pragma unroll
        for (int c = 0; c < 3; c++) {
            const u64* p = reinterpret_cast<const u64*>(&w_sh[(c0 + c) * ES + k]);
            wA[c] = p[0]; wB[c] = p[1];
        }
#pragma unroll
        for (int i = 0; i < 2; i++)
#pragma unroll
            for (int c = 0; c < 3; c++) {
                accP[i][c] = ffma2(eA[i], wA[c], accP[i][c]);
                accQ[i][c] = ffma2(eB[i], wB[c], accQ[i][c]);
            }
    }
#pragma unroll
    for (int i = 0; i < 2; i++)
#pragma unroll
        for (int c = 0; c < 3; c++) {
            float2 p = u2f2(accP[i][c]), q = u2f2(accQ[i][c]);
            float v = (p.x + p.y) + (q.x + q.y) + bi[col0 + c0 + c];
            d_x3[(size_t)(bt0 + r0 + i) * 768 + dir * 384 + col0 + c0 + c] = v;
        }
}

// ---------------- 3) GRU, one CTA per (batch, dir) ----------------
// 384 threads, thread j owns whh row j in registers (64 x f32x2).
__global__ void __launch_bounds__(384, 1)
gru_kernel(const float* __restrict__ whh_f, const float* __restrict__ whh_b,
           const float* __restrict__ bhh_f, const float* __restrict__ bhh_b) {
    int b = blockIdx.x, dir = blockIdx.y;
    int j = threadIdx.x;
    const float* whh = dir ? whh_b : whh_f;
    const float* bhh = dir ? bhh_b : bhh_f;

    __shared__ __align__(16) float h_f[128];
    __shared__ float gh_sh[384];

    u64 wr[64];
    const u64* wrow = reinterpret_cast<const u64*>(whh + (size_t)j * 128);
#pragma unroll
    for (int k = 0; k < 64; k++) wr[k] = wrow[k];
    float bh = bhh[j];
    if (j < 128) h_f[j] = 0.f;
    __syncthreads();

    const float* x3base = d_x3 + (size_t)b * T * 768 + dir * 384;
    float* hsbase = d_hs + ((size_t)dir * BT + (size_t)b * T) * D;
    const u64* hv = reinterpret_cast<const u64*>(h_f);

    for (int s = 0; s < T; s++) {
        int t = dir ? (T - 1 - s) : s;
        const float* xp = x3base + (size_t)t * 768;
        float xr = 0.f, xz = 0.f, xn = 0.f;
        if (j < 128) { xr = xp[j]; xz = xp[128 + j]; xn = xp[256 + j]; }

        u64 a0 = 0, a1 = 0, a2 = 0, a3 = 0;
#pragma unroll
        for (int k = 0; k < 64; k += 4) {
            a0 = ffma2(wr[k],     hv[k],     a0);
            a1 = ffma2(wr[k + 1], hv[k + 1], a1);
            a2 = ffma2(wr[k + 2], hv[k + 2], a2);
            a3 = ffma2(wr[k + 3], hv[k + 3], a3);
        }
        float2 f0 = u2f2(a0), f1 = u2f2(a1), f2 = u2f2(a2), f3 = u2f2(a3);
        gh_sh[j] = ((f0.x + f0.y) + (f1.x + f1.y)) + ((f2.x + f2.y) + (f3.x + f3.y)) + bh;
        __syncthreads();

        if (j < 128) {
            float r = sigmoidf(xr + gh_sh[j]);
            float z = sigmoidf(xz + gh_sh[128 + j]);
            float n = tanhf(xn + r * gh_sh[256 + j]);
            float hnew = (1.f - z) * n + z * h_f[j];
            h_f[j] = hnew;
            hsbase[(size_t)t * D + j] = hnew;
        }
        __syncthreads();
    }
}

// ---------------- 4) attention + combine, one CTA per batch ----------------
__global__ void attn_kernel(const float* __restrict__ aw, const float* __restrict__ ab,
                            const float* __restrict__ comb_w, const float* __restrict__ comb_b) {
    int b = blockIdx.x;
    int tid = threadIdx.x;  // 256
    __shared__ float aw_sh[256];
    __shared__ float sc[128];
    __shared__ float c_sh[256];
    __shared__ float hl_sh[256];
    __shared__ int last_sh;

    aw_sh[tid] = aw[tid];
    __syncthreads();

    const float* hf = d_hs + (size_t)b * T * D;
    const float* hb = d_hs + ((size_t)BT + (size_t)b * T) * D;
    int w = tid >> 5, lane = tid & 31;

    // scores (warp per timestep)
    for (int t = w; t < T; t += 8) {
        float s = 0.f;
        const float* pf = hf + (size_t)t * D;
        const float* pb = hb + (size_t)t * D;
        for (int d = lane; d < D; d += 32)
            s += pf[d] * aw_sh[d] + pb[d] * aw_sh[128 + d];
#pragma unroll
        for (int o = 16; o; o >>= 1) s += __shfl_xor_sync(0xffffffffu, s, o);
        if (lane == 0) sc[t] = d_mask[b * T + t] ? (s + ab[0]) : -1e9f;
    }
    __syncthreads();

    // softmax (warp 0) + last index
    if (w == 0) {
        float m = -1e30f;
        for (int t = lane; t < T; t += 32) m = fmaxf(m, sc[t]);
#pragma unroll
        for (int o = 16; o; o >>= 1) m = fmaxf(m, __shfl_xor_sync(0xffffffffu, m, o));
        float s = 0.f;
        for (int t = lane; t < T; t += 32) { float e = expf(sc[t] - m); sc[t] = e; s += e; }
#pragma unroll
        for (int o = 16; o; o >>= 1) s += __shfl_xor_sync(0xffffffffu, s, o);
        float inv = 1.f / s;
        for (int t = lane; t < T; t += 32) sc[t] *= inv;
        if (lane == 0) {
            int c = 0;
            for (int t = 0; t < T; t++) c += d_mask[b * T + t];
            last_sh = c - 1;
        }
    }
    __syncthreads();

    int last = last_sh;
    int f = tid;  // 256 features of [hf|hb]
    const float* hcol = (f < 128) ? (hf + f) : (hb + (f - 128));
    float cacc = 0.f;
    for (int t = 0; t < T; t++) cacc += sc[t] * hcol[(size_t)t * D];
    c_sh[f] = cacc;
    hl_sh[f] = hcol[(size_t)last * D];
    __syncthreads();

    if (tid < 128) {
        float acc = comb_b[tid];
        const float* wr = comb_w + (size_t)tid * 512;
        for (int k = 0; k < 256; k++) acc += c_sh[k] * wr[k];
        for (int k = 0; k < 256; k++) acc += hl_sh[k] * wr[256 + k];
        d_feat[b * D + tid] = tanhf(acc);
    }
}

// ---------------- 5) logits = feat @ fc_w^T + fc_b ----------------
// grid 125 blocks x 256 threads; each block: all 32 batches x 8 output cols
__global__ void logits_kernel(const float* __restrict__ fc_w, const float* __restrict__ fc_b,
                              float* __restrict__ out) {
    int o0 = blockIdx.x * 8;
    int tid = threadIdx.x;
    __shared__ float fsh[32 * 129];
    __shared__ float wsh[8 * 128];
    for (int i = tid; i < 32 * 128; i += 256) {
        int bb = i >> 7, k = i & 127;
        fsh[bb * 129 + k] = d_feat[i];
    }
    for (int i = tid; i < 8 * 128; i += 256) wsh[i] = fc_w[(size_t)o0 * 128 + i];
    __syncthreads();

    int bb = tid & 31, oj = tid >> 5;
    float acc = fc_b[o0 + oj];
    for (int k = 0; k < 128; k++) acc += fsh[bb * 129 + k] * wsh[oj * 128 + k];
    out[(size_t)bb * OUTN + o0 + oj] = acc;
}

// ---------------- launch ----------------
extern "C" void kernel_launch(void* const* d_in, const int* in_sizes, int n_in,
                              void* d_out, int out_size) {
    const float* x      = (const float*)d_in[0];
    const float* emb    = (const float*)d_in[1];
    const float* wih_f  = (const float*)d_in[2];
    const float* whh_f  = (const float*)d_in[3];
    const float* bih_f  = (const float*)d_in[4];
    const float* bhh_f  = (const float*)d_in[5];
    const float* wih_b  = (const float*)d_in[6];
    const float* whh_b  = (const float*)d_in[7];
    const float* bih_b  = (const float*)d_in[8];
    const float* bhh_b  = (const float*)d_in[9];
    const float* attn_w = (const float*)d_in[10];
    const float* attn_b = (const float*)d_in[11];
    const float* comb_w = (const float*)d_in[12];
    const float* comb_b = (const float*)d_in[13];
    const float* fc_w   = (const float*)d_in[14];
    const float* fc_b   = (const float*)d_in[15];
    float* out = (float*)d_out;

    embed_kernel<<<BT, 128>>>(x, emb);
    xgemm_kernel<<<dim3(100, 8, 2), 256>>>(wih_f, wih_b, bih_f, bih_b);
    gru_kernel<<<dim3(32, 2), 384>>>(whh_f, whh_b, bhh_f, bhh_b);
    attn_kernel<<<32, 256>>>(attn_w, attn_b, comb_w, comb_b);
    logits_kernel<<<125, 256>>>(fc_w, fc_b, out);
}

// round 3
// speedup vs baseline: 1.2228x; 1.2228x over previous
#include <cuda_runtime.h>

#define B   32
#define T   100
#define V   10000
#define D   128
#define OUTN 1000
#define BT  (B*T)

typedef unsigned long long u64;

// ---------------- scratch (no allocations allowed) ----------------
__device__ float d_e[BT * D];          // embedded visits [B*T][128]
__device__ int   d_mask[BT];           // visit mask
__device__ float d_x3[BT * 768];       // input-side gates, [bt][dir*384 + g]
__device__ float d_hs[2 * BT * D];     // GRU outputs, dir-major
__device__ float d_feat[B * D];        // combined feature

// ---------------- helpers ----------------
__device__ __forceinline__ u64 ffma2(u64 a, u64 b, u64 c) {
    u64 d;
    asm("fma.rn.f32x2 %0, %1, %2, %3;" : "=l"(d) : "l"(a), "l"(b), "l"(c));
    return d;
}
__device__ __forceinline__ float2 u2f2(u64 a) {
    float2 f;
    asm("mov.b64 {%0, %1}, %2;" : "=f"(f.x), "=f"(f.y) : "l"(a));
    return f;
}
__device__ __forceinline__ float fast_sigmoid(float x) {
    return 1.0f / (1.0f + __expf(-x));
}
__device__ __forceinline__ float fast_tanh(float x) {
    // tanh(x) = 2*sigmoid(2x) - 1
    return 2.0f / (1.0f + __expf(-2.0f * x)) - 1.0f;
}

// ---------------- 1) sparse embedding + mask ----------------
// grid = BT blocks, 256 threads
__global__ void embed_kernel(const float* __restrict__ x, const float* __restrict__ emb) {
    int bt = blockIdx.x;
    __shared__ int cnt;
    __shared__ int idx[1024];
    __shared__ float part[128];
    if (threadIdx.x == 0) cnt = 0;
    __syncthreads();

    const float4* row = reinterpret_cast<const float4*>(x + (size_t)bt * V);
    for (int i = threadIdx.x; i < V / 4; i += blockDim.x) {
        float4 v = row[i];
        if (v.x != 0.f) { int p = atomicAdd(&cnt, 1); if (p < 1024) idx[p] = 4 * i; }
        if (v.y != 0.f) { int p = atomicAdd(&cnt, 1); if (p < 1024) idx[p] = 4 * i + 1; }
        if (v.z != 0.f) { int p = atomicAdd(&cnt, 1); if (p < 1024) idx[p] = 4 * i + 2; }
        if (v.w != 0.f) { int p = atomicAdd(&cnt, 1); if (p < 1024) idx[p] = 4 * i + 3; }
    }
    __syncthreads();
    int n = min(cnt, 1024);
    int d = threadIdx.x & 127;
    int half = threadIdx.x >> 7;
    float acc = 0.f;
    for (int j = half; j < n; j += 2) acc += emb[(size_t)idx[j] * D + d];
    if (half) part[d] = acc;
    __syncthreads();
    float tot = 0.f;
    if (half == 0) {
        tot = acc + part[d];
        d_e[bt * D + d] = tot;
    }
    int nz = __syncthreads_or(half == 0 && tot != 0.f);
    if (threadIdx.x == 0) d_mask[bt] = nz ? 1 : 0;
}

// ---------------- 2) x3 = e @ wih^T + bih, both dirs ----------------
// grid (100, 8, 2), 256 threads. tile: 32 bt-rows x 48 gate-cols, K=128.
#define ES 130  // padded row stride (words)
__global__ void xgemm_kernel(const float* __restrict__ wih_f, const float* __restrict__ wih_b,
                             const float* __restrict__ bih_f, const float* __restrict__ bih_b) {
    const int bt0  = blockIdx.x * 32;
    const int col0 = blockIdx.y * 48;
    const int dir  = blockIdx.z;
    const float* W  = dir ? wih_b : wih_f;
    const float* bi = dir ? bih_b : bih_f;

    __shared__ __align__(16) float e_sh[32 * ES];
    __shared__ __align__(16) float w_sh[48 * ES];
    int tid = threadIdx.x;
    for (int i = tid; i < 32 * 128; i += 256) {
        int r = i >> 7, k = i & 127;
        e_sh[r * ES + k] = d_e[(bt0 + r) * D + k];
    }
    for (int i = tid; i < 48 * 128; i += 256) {
        int c = i >> 7, k = i & 127;
        w_sh[c * ES + k] = W[(size_t)(col0 + c) * D + k];
    }
    __syncthreads();

    int rt = tid & 15;   // rows 2*rt, 2*rt+1
    int ct = tid >> 4;   // cols 3*ct .. 3*ct+2
    int r0 = rt * 2, c0 = ct * 3;

    u64 accP[2][3] = {}, accQ[2][3] = {};
    for (int k = 0; k < 128; k += 4) {
        u64 eA[2], eB[2], wA[3], wB[3];
#pragma unroll
        for (int i = 0; i < 2; i++) {
            const u64* p = reinterpret_cast<const u64*>(&e_sh[(r0 + i) * ES + k]);
            eA[i] = p[0]; eB[i] = p[1];
        }
#pragma unroll
        for (int c = 0; c < 3; c++) {
            const u64* p = reinterpret_cast<const u64*>(&w_sh[(c0 + c) * ES + k]);
            wA[c] = p[0]; wB[c] = p[1];
        }
#pragma unroll
        for (int i = 0; i < 2; i++)
#pragma unroll
            for (int c = 0; c < 3; c++) {
                accP[i][c] = ffma2(eA[i], wA[c], accP[i][c]);
                accQ[i][c] = ffma2(eB[i], wB[c], accQ[i][c]);
            }
    }
#pragma unroll
    for (int i = 0; i < 2; i++)
#pragma unroll
        for (int c = 0; c < 3; c++) {
            float2 p = u2f2(accP[i][c]), q = u2f2(accQ[i][c]);
            float v = (p.x + p.y) + (q.x + q.y) + bi[col0 + c0 + c];
            d_x3[(size_t)(bt0 + r0 + i) * 768 + dir * 384 + col0 + c0 + c] = v;
        }
}

// ---------------- 3) GRU, one CTA per (batch, dir) ----------------
// 384 threads, thread j owns whh row j in registers (64 x f32x2).
__global__ void __launch_bounds__(384, 1)
gru_kernel(const float* __restrict__ whh_f, const float* __restrict__ whh_b,
           const float* __restrict__ bhh_f, const float* __restrict__ bhh_b) {
    int b = blockIdx.x, dir = blockIdx.y;
    int j = threadIdx.x;
    const float* whh = dir ? whh_b : whh_f;
    const float* bhh = dir ? bhh_b : bhh_f;

    __shared__ __align__(16) float h_f[128];
    __shared__ float gh_sh[384];

    u64 wr[64];
    const u64* wrow = reinterpret_cast<const u64*>(whh + (size_t)j * 128);
#pragma unroll
    for (int k = 0; k < 64; k++) wr[k] = wrow[k];
    float bh = bhh[j];
    if (j < 128) h_f[j] = 0.f;

    const float* x3base = d_x3 + (size_t)b * T * 768 + dir * 384;
    float* hsbase = d_hs + ((size_t)dir * BT + (size_t)b * T) * D;
    const ulonglong2* hv2 = reinterpret_cast<const ulonglong2*>(h_f);

    // preload x for first timestep
    int t0 = dir ? (T - 1) : 0;
    float xr = 0.f, xz = 0.f, xn = 0.f;
    if (j < 128) {
        const float* xp = x3base + (size_t)t0 * 768;
        xr = xp[j]; xz = xp[128 + j]; xn = xp[256 + j];
    }
    __syncthreads();

    for (int s = 0; s < T; s++) {
        int t = dir ? (T - 1 - s) : s;

        u64 a0 = 0, a1 = 0, a2 = 0, a3 = 0;
#pragma unroll
        for (int k = 0; k < 32; k += 2) {
            ulonglong2 h0 = hv2[k];
            ulonglong2 h1 = hv2[k + 1];
            a0 = ffma2(wr[2 * k],     h0.x, a0);
            a1 = ffma2(wr[2 * k + 1], h0.y, a1);
            a2 = ffma2(wr[2 * k + 2], h1.x, a2);
            a3 = ffma2(wr[2 * k + 3], h1.y, a3);
        }
        float2 f0 = u2f2(a0), f1 = u2f2(a1), f2 = u2f2(a2), f3 = u2f2(a3);
        gh_sh[j] = ((f0.x + f0.y) + (f1.x + f1.y)) + ((f2.x + f2.y) + (f3.x + f3.y)) + bh;

        // prefetch next-step x (drains during the barrier)
        float nxr = 0.f, nxz = 0.f, nxn = 0.f;
        if (s + 1 < T && j < 128) {
            int tn = dir ? (T - 2 - s) : (s + 1);
            const float* xp = x3base + (size_t)tn * 768;
            nxr = xp[j]; nxz = xp[128 + j]; nxn = xp[256 + j];
        }
        __syncthreads();

        if (j < 128) {
            float r = fast_sigmoid(xr + gh_sh[j]);
            float z = fast_sigmoid(xz + gh_sh[128 + j]);
            float n = fast_tanh(xn + r * gh_sh[256 + j]);
            float hnew = (1.f - z) * n + z * h_f[j];
            h_f[j] = hnew;
            hsbase[(size_t)t * D + j] = hnew;
        }
        xr = nxr; xz = nxz; xn = nxn;
        __syncthreads();
    }
}

// ---------------- 4) attention + combine, one CTA per batch ----------------
__global__ void attn_kernel(const float* __restrict__ aw, const float* __restrict__ ab,
                            const float* __restrict__ comb_w, const float* __restrict__ comb_b) {
    int b = blockIdx.x;
    int tid = threadIdx.x;  // 256
    __shared__ float aw_sh[256];
    __shared__ float sc[128];
    __shared__ int   msk[128];
    __shared__ float in_sh[512];   // [c(256) | h_last(256)]
    __shared__ int last_sh;

    aw_sh[tid] = aw[tid];
    if (tid < T) msk[tid] = d_mask[b * T + tid];
    __syncthreads();

    const float* hf = d_hs + (size_t)b * T * D;
    const float* hb = d_hs + ((size_t)BT + (size_t)b * T) * D;
    int w = tid >> 5, lane = tid & 31;

    // scores (warp per timestep)
    for (int t = w; t < T; t += 8) {
        float s = 0.f;
        const float* pf = hf + (size_t)t * D;
        const float* pb = hb + (size_t)t * D;
#pragma unroll
        for (int d = lane; d < D; d += 32)
            s += pf[d] * aw_sh[d] + pb[d] * aw_sh[128 + d];
#pragma unroll
        for (int o = 16; o; o >>= 1) s += __shfl_xor_sync(0xffffffffu, s, o);
        if (lane == 0) sc[t] = msk[t] ? (s + ab[0]) : -1e9f;
    }
    __syncthreads();

    // softmax (warp 0) + last index
    if (w == 0) {
        float m = -1e30f;
        for (int t = lane; t < T; t += 32) m = fmaxf(m, sc[t]);
#pragma unroll
        for (int o = 16; o; o >>= 1) m = fmaxf(m, __shfl_xor_sync(0xffffffffu, m, o));
        float s = 0.f;
        for (int t = lane; t < T; t += 32) { float e = __expf(sc[t] - m); sc[t] = e; s += e; }
#pragma unroll
        for (int o = 16; o; o >>= 1) s += __shfl_xor_sync(0xffffffffu, s, o);
        float inv = 1.f / s;
        for (int t = lane; t < T; t += 32) sc[t] *= inv;
        int c = 0;
        for (int t = lane; t < T; t += 32) c += msk[t];
#pragma unroll
        for (int o = 16; o; o >>= 1) c += __shfl_xor_sync(0xffffffffu, c, o);
        if (lane == 0) last_sh = c - 1;
    }
    __syncthreads();

    int last = last_sh;
    int f = tid;  // 256 features of [hf|hb]
    const float* hcol = (f < 128) ? (hf + f) : (hb + (f - 128));
    float cacc = 0.f;
#pragma unroll 4
    for (int t = 0; t < T; t++) cacc += sc[t] * hcol[(size_t)t * D];
    in_sh[f] = cacc;
    in_sh[256 + f] = hcol[(size_t)last * D];
    __syncthreads();

    // combine: warp per output, coalesced float4 reads of comb_w rows
    for (int o = w; o < 128; o += 8) {
        const float4* row4 = reinterpret_cast<const float4*>(comb_w + (size_t)o * 512);
        float acc = 0.f;
#pragma unroll
        for (int q = 0; q < 4; q++) {
            int i = lane + 32 * q;           // float4 index, 0..127
            float4 wv = row4[i];
            const float* iv = &in_sh[4 * i];
            acc += wv.x * iv[0] + wv.y * iv[1] + wv.z * iv[2] + wv.w * iv[3];
        }
#pragma unroll
        for (int of = 16; of; of >>= 1) acc += __shfl_xor_sync(0xffffffffu, acc, of);
        if (lane == 0) d_feat[b * D + o] = fast_tanh(acc + comb_b[o]);
    }
}

// ---------------- 5) logits = feat @ fc_w^T + fc_b ----------------
// grid 125 blocks x 256 threads; each block: all 32 batches x 8 output cols
__global__ void logits_kernel(const float* __restrict__ fc_w, const float* __restrict__ fc_b,
                              float* __restrict__ out) {
    int o0 = blockIdx.x * 8;
    int tid = threadIdx.x;
    __shared__ float fsh[32 * 129];
    __shared__ float wsh[8 * 128];
    for (int i = tid; i < 32 * 128; i += 256) {
        int bb = i >> 7, k = i & 127;
        fsh[bb * 129 + k] = d_feat[i];
    }
    for (int i = tid; i < 8 * 128; i += 256) wsh[i] = fc_w[(size_t)o0 * 128 + i];
    __syncthreads();

    int bb = tid & 31, oj = tid >> 5;
    float acc = fc_b[o0 + oj];
#pragma unroll 8
    for (int k = 0; k < 128; k++) acc += fsh[bb * 129 + k] * wsh[oj * 128 + k];
    out[(size_t)bb * OUTN + o0 + oj] = acc;
}

// ---------------- launch ----------------
extern "C" void kernel_launch(void* const* d_in, const int* in_sizes, int n_in,
                              void* d_out, int out_size) {
    const float* x      = (const float*)d_in[0];
    const float* emb    = (const float*)d_in[1];
    const float* wih_f  = (const float*)d_in[2];
    const float* whh_f  = (const float*)d_in[3];
    const float* bih_f  = (const float*)d_in[4];
    const float* bhh_f  = (const float*)d_in[5];
    const float* wih_b  = (const float*)d_in[6];
    const float* whh_b  = (const float*)d_in[7];
    const float* bih_b  = (const float*)d_in[8];
    const float* bhh_b  = (const float*)d_in[9];
    const float* attn_w = (const float*)d_in[10];
    const float* attn_b = (const float*)d_in[11];
    const float* comb_w = (const float*)d_in[12];
    const float* comb_b = (const float*)d_in[13];
    const float* fc_w   = (const float*)d_in[14];
    const float* fc_b   = (const float*)d_in[15];
    float* out = (float*)d_out;

    embed_kernel<<<BT, 256>>>(x, emb);
    xgemm_kernel<<<dim3(100, 8, 2), 256>>>(wih_f, wih_b, bih_f, bih_b);
    gru_kernel<<<dim3(32, 2), 384>>>(whh_f, whh_b, bhh_f, bhh_b);
    attn_kernel<<<32, 256>>>(attn_w, attn_b, comb_w, comb_b);
    logits_kernel<<<125, 256>>>(fc_w, fc_b, out);
}